// round 16
// baseline (speedup 1.0000x reference)
#include <cuda_runtime.h>
#include <cuda_bf16.h>
#include <math.h>
#include <stdint.h>

#define DD   8
#define FF   1024
#define HH   1024
#define CC   22
#define INN  4096
#define NROW 4096
#define G4   4096
#define NCAT (G4 + FF)    // 5120

typedef __nv_bfloat16 bf16;

// element counts
constexpr size_t EX  = (size_t)NROW * INN;   // 16.7M
constexpr size_t EW4 = (size_t)G4 * FF;      // 4.2M
constexpr size_t EW1 = (size_t)FF * HH;      // 1.05M
constexpr size_t EWC = (size_t)NCAT * HH;    // 5.24M
constexpr size_t EH  = (size_t)NROW * HH;    // 4.2M

// ---------------- arena ----------------
// per tensor: bf16-hi (2E) + fp8-hi (E) + fp8-res (E)
constexpr size_t O_XH  = 0;
constexpr size_t O_X8  = O_XH  + 2 * EX;
constexpr size_t O_XR  = O_X8  + EX;
constexpr size_t O_WFH = O_XR  + EX;
constexpr size_t O_WF8 = O_WFH + 2 * EW4;
constexpr size_t O_WFR = O_WF8 + EW4;
constexpr size_t O_DIH = O_WFR + EW4;
constexpr size_t O_DI8 = O_DIH + 2 * EW4;
constexpr size_t O_DIR = O_DI8 + EW4;
constexpr size_t O_EIH = O_DIR + EW4;
constexpr size_t O_EI8 = O_EIH + 2 * EW4;
constexpr size_t O_EIR = O_EI8 + EW4;
constexpr size_t O_EHH = O_EIR + EW4;
constexpr size_t O_EH8 = O_EHH + 2 * EW4;
constexpr size_t O_EHR = O_EH8 + EW4;
constexpr size_t O_WTH = O_EHR + EW4;
constexpr size_t O_WT8 = O_WTH + 2 * EW1;
constexpr size_t O_WTR = O_WT8 + EW1;
constexpr size_t O_WCH = O_WTR + EW1;        // [NCAT,HH]: rows 0..4095 Wcomb, 4096.. Wdc
constexpr size_t O_WC8 = O_WCH + 2 * EWC;
constexpr size_t O_WCR = O_WC8 + EWC;
constexpr size_t O_FH  = O_WCR + EWC;
constexpr size_t O_F8  = O_FH  + 2 * EW4;
constexpr size_t O_FR  = O_F8  + EW4;
constexpr size_t O_HHO = O_FR  + EW4;
constexpr size_t O_H8  = O_HHO + 2 * EH;
constexpr size_t O_HR  = O_H8  + EH;
constexpr size_t O_LH  = O_HR  + EH;
constexpr size_t O_L8  = O_LH  + 2 * EH;
constexpr size_t O_LR  = O_L8  + EH;
constexpr size_t O_C   = O_LR  + EH;
constexpr size_t O_G   = O_C   + 4 * EH;
constexpr size_t O_HF  = O_G   + 4 * (size_t)NROW * G4;
constexpr size_t O_B0  = O_HF  + 4 * EH;
constexpr size_t O_B1  = O_B0  + 4 * (size_t)G4;
constexpr size_t O_B2  = O_B1  + 4 * (size_t)NCAT;
constexpr size_t ARENA = O_B2  + 4 * (size_t)G4;

__device__ __align__(1024) unsigned char g_arena[ARENA];

// scales
#define QS_ACT 16.0f
#define QS_WGT 512.0f
#define RS_AW  (1.0f / (16.0f * 512.0f * 256.0f))    // 2^-21
#define RS_WW  (1.0f / (512.0f * 512.0f * 256.0f))   // 2^-26

// ---------------- helpers ----------------
__device__ __forceinline__ uint32_t smem_u32(const void* p) {
    uint32_t a;
    asm("{ .reg .u64 t; cvta.to.shared.u64 t, %1; cvt.u32.u64 %0, t; }" : "=r"(a) : "l"(p));
    return a;
}
__device__ __forceinline__ void ldsm4(uint32_t& r0, uint32_t& r1, uint32_t& r2, uint32_t& r3,
                                      uint32_t addr) {
    asm volatile("ldmatrix.sync.aligned.m8n8.x4.shared.b16 {%0,%1,%2,%3}, [%4];"
                 : "=r"(r0), "=r"(r1), "=r"(r2), "=r"(r3) : "r"(addr));
}
__device__ __forceinline__ void mma_bf16(float* c, const uint32_t* a, const uint32_t* b) {
    asm volatile("mma.sync.aligned.m16n8k16.row.col.f32.bf16.bf16.f32 "
                 "{%0,%1,%2,%3}, {%4,%5,%6,%7}, {%8,%9}, {%0,%1,%2,%3};"
                 : "+f"(c[0]), "+f"(c[1]), "+f"(c[2]), "+f"(c[3])
                 : "r"(a[0]), "r"(a[1]), "r"(a[2]), "r"(a[3]), "r"(b[0]), "r"(b[1]));
}
__device__ __forceinline__ void mma_fp8(float* c, const uint32_t* a, const uint32_t* b) {
    asm volatile("mma.sync.aligned.m16n8k32.row.col.f32.e4m3.e4m3.f32 "
                 "{%0,%1,%2,%3}, {%4,%5,%6,%7}, {%8,%9}, {%0,%1,%2,%3};"
                 : "+f"(c[0]), "+f"(c[1]), "+f"(c[2]), "+f"(c[3])
                 : "r"(a[0]), "r"(a[1]), "r"(a[2]), "r"(a[3]), "r"(b[0]), "r"(b[1]));
}
// packs (lo, hi) -> [hi|lo] e4m3 pair
__device__ __forceinline__ unsigned short cvt2_e4m3(float lo, float hi) {
    unsigned short r;
    asm("cvt.rn.satfinite.e4m3x2.f32 %0, %1, %2;" : "=h"(r) : "f"(hi), "f"(lo));
    return r;
}
__device__ __forceinline__ float sigm(float x) { return 1.0f / (1.0f + expf(-x)); }

#define ROWPITCH    80
#define TILE_BYTES  (128 * ROWPITCH)    // 10240
#define STAGE_BYTES (2 * TILE_BYTES)    // 20480: [A|B]
#define STAGES      4
#define SMEM_DYN    (STAGES * STAGE_BYTES)   // 81920

template<int FP8>
__device__ __forceinline__ void chunk_compute(
    float c[4][4][4], uint32_t sA, uint32_t sB,
    uint32_t a_row, uint32_t a_ch, uint32_t b_row, uint32_t b_ch)
{
#pragma unroll
    for (int ks = 0; ks < 2; ks++) {
        uint32_t a[4][4], b[4][2];
#pragma unroll
        for (int np = 0; np < 2; np++) {
            const uint32_t addr = sB + (b_row + np * 16) * ROWPITCH + ks * 32 + b_ch;
            ldsm4(b[2 * np][0], b[2 * np][1], b[2 * np + 1][0], b[2 * np + 1][1], addr);
        }
#pragma unroll
        for (int mf = 0; mf < 4; mf++) {
            const uint32_t addr = sA + (a_row + mf * 16) * ROWPITCH + ks * 32 + a_ch;
            ldsm4(a[mf][0], a[mf][1], a[mf][2], a[mf][3], addr);
        }
#pragma unroll
        for (int mf = 0; mf < 4; mf++)
#pragma unroll
            for (int nf = 0; nf < 4; nf++) {
                if (FP8) mma_fp8(c[mf][nf], a[mf], b[nf]);
                else     mma_bf16(c[mf][nf], a[mf], b[nf]);
            }
    }
}

// ---------------- hybrid fp8+bf16 split GEMM (CTA 128x128, warp 64x32, 2 CTA/SM) ----------------
struct PassCfg {
    const uint8_t* a8[4]; const uint8_t* b8[4]; int n8;
    const bf16* ah[2]; const bf16* bh[2]; int nh;
};

__global__ __launch_bounds__(256, 2)
void tcgemm(PassCfg P, int Kp, int N1, float rescale,
            const float* __restrict__ bias,
            const float* __restrict__ Cadd, int ldadd,
            float* __restrict__ C1, int ldc1,
            float* __restrict__ C2, int ldc2,
            bf16* __restrict__ Oh, uint8_t* __restrict__ O8, uint8_t* __restrict__ Or8,
            int ldo, float oscale, float qs, int relu)
{
    extern __shared__ __align__(16) unsigned char dsm[];
    const uint32_t sbase = smem_u32(dsm);

    const int tid = threadIdx.x, wid = tid >> 5, lane = tid & 31;
    const int wm = wid >> 2;
    const int wn = wid & 3;
    const int tm = blockIdx.y, tn = blockIdx.x;

    float c[4][4][4];
#pragma unroll
    for (int i = 0; i < 4; i++)
#pragma unroll
        for (int j = 0; j < 4; j++)
#pragma unroll
            for (int k = 0; k < 4; k++) c[i][j][k] = 0.f;

    const uint32_t a_row = (uint32_t)(wm * 64 + (lane & 15));
    const uint32_t a_ch  = (uint32_t)((lane >> 4) * 16);
    const uint32_t b_row = (uint32_t)(wn * 32 + ((lane >> 4) << 3) + (lane & 7));
    const uint32_t b_ch  = (uint32_t)(((lane >> 3) & 1) * 16);

    // ===== phase 1: fp8 residual passes (chunk = 64 elems = 64 B) =====
    {
        const int ck  = Kp >> 6;
        const int nkt = P.n8 * ck;
        int lp = 0, lkk = 0;
        auto load8 = [&](int f) {
            const int buf = f & 3;
            const uint8_t* Ag = P.a8[lp] + (size_t)(tm * 128) * Kp + (lkk << 6);
            const uint8_t* Bg = P.b8[lp] + (size_t)(tn * 128) * Kp + (lkk << 6);
            const uint32_t sA = sbase + (uint32_t)buf * STAGE_BYTES;
            const uint32_t sB = sA + TILE_BYTES;
#pragma unroll
            for (int j = 0; j < 2; j++) {
                const int i = tid + 256 * j;
                const int row = i >> 2, ch = i & 3;
                const uint32_t d = (uint32_t)row * ROWPITCH + (uint32_t)ch * 16;
                asm volatile("cp.async.cg.shared.global [%0], [%1], 16;"
                             :: "r"(sA + d), "l"(Ag + (size_t)row * Kp + ch * 16) : "memory");
                asm volatile("cp.async.cg.shared.global [%0], [%1], 16;"
                             :: "r"(sB + d), "l"(Bg + (size_t)row * Kp + ch * 16) : "memory");
            }
            asm volatile("cp.async.commit_group;" ::: "memory");
            lkk++; if (lkk == ck) { lkk = 0; lp++; }
        };
        for (int f = 0; f < STAGES - 1 && f < nkt; f++) load8(f);
        for (int kt = 0; kt < nkt; kt++) {
            int w = nkt - kt - 1;
            if (w > STAGES - 2) w = STAGES - 2;
            if (w == 2)      asm volatile("cp.async.wait_group 2;" ::: "memory");
            else if (w == 1) asm volatile("cp.async.wait_group 1;" ::: "memory");
            else             asm volatile("cp.async.wait_group 0;" ::: "memory");
            __syncthreads();
            if (kt + STAGES - 1 < nkt) load8(kt + STAGES - 1);
            const uint32_t sA = sbase + (uint32_t)(kt & 3) * STAGE_BYTES;
            chunk_compute<1>(c, sA, sA + TILE_BYTES, a_row, a_ch, b_row, b_ch);
        }
        __syncthreads();   // all reads done before phase-2 reuses buffers
    }

    // rescale fp8 contribution
#pragma unroll
    for (int i = 0; i < 4; i++)
#pragma unroll
        for (int j = 0; j < 4; j++)
#pragma unroll
            for (int k = 0; k < 4; k++) c[i][j][k] *= rescale;

    // ===== phase 2: exact bf16 hi pass (chunk = 32 elems = 64 B) =====
    {
        const int ck  = Kp >> 5;
        const int nkt = P.nh * ck;
        int lp = 0, lkk = 0;
        auto loadh = [&](int f) {
            const int buf = f & 3;
            const bf16* Ag = P.ah[lp] + (size_t)(tm * 128) * Kp + (lkk << 5);
            const bf16* Bg = P.bh[lp] + (size_t)(tn * 128) * Kp + (lkk << 5);
            const uint32_t sA = sbase + (uint32_t)buf * STAGE_BYTES;
            const uint32_t sB = sA + TILE_BYTES;
#pragma unroll
            for (int j = 0; j < 2; j++) {
                const int i = tid + 256 * j;
                const int row = i >> 2, ch = i & 3;
                const uint32_t d = (uint32_t)row * ROWPITCH + (uint32_t)ch * 16;
                asm volatile("cp.async.cg.shared.global [%0], [%1], 16;"
                             :: "r"(sA + d), "l"(Ag + (size_t)row * Kp + ch * 8) : "memory");
                asm volatile("cp.async.cg.shared.global [%0], [%1], 16;"
                             :: "r"(sB + d), "l"(Bg + (size_t)row * Kp + ch * 8) : "memory");
            }
            asm volatile("cp.async.commit_group;" ::: "memory");
            lkk++; if (lkk == ck) { lkk = 0; lp++; }
        };
        for (int f = 0; f < STAGES - 1 && f < nkt; f++) loadh(f);
        for (int kt = 0; kt < nkt; kt++) {
            int w = nkt - kt - 1;
            if (w > STAGES - 2) w = STAGES - 2;
            if (w == 2)      asm volatile("cp.async.wait_group 2;" ::: "memory");
            else if (w == 1) asm volatile("cp.async.wait_group 1;" ::: "memory");
            else             asm volatile("cp.async.wait_group 0;" ::: "memory");
            __syncthreads();
            if (kt + STAGES - 1 < nkt) loadh(kt + STAGES - 1);
            const uint32_t sA = sbase + (uint32_t)(kt & 3) * STAGE_BYTES;
            chunk_compute<0>(c, sA, sA + TILE_BYTES, a_row, a_ch, b_row, b_ch);
        }
    }

    // ---------------- epilogue ----------------
    const int tr = lane >> 2, tc = (lane & 3) * 2;
#pragma unroll
    for (int mf = 0; mf < 4; mf++) {
#pragma unroll
        for (int half = 0; half < 2; half++) {
            const size_t row = (size_t)tm * 128 + wm * 64 + mf * 16 + tr + half * 8;
            float* c1row = C1 ? C1 + row * (size_t)ldc1 : (float*)0;
            float* c2row = C2 ? C2 + row * (size_t)ldc2 : (float*)0;
            const float* arow = Cadd ? Cadd + row * (size_t)ldadd : (const float*)0;
            bf16* ohr = Oh ? Oh + row * (size_t)ldo : (bf16*)0;
            uint8_t* o8r = O8 ? O8 + row * (size_t)ldo : (uint8_t*)0;
            uint8_t* orr = Or8 ? Or8 + row * (size_t)ldo : (uint8_t*)0;
#pragma unroll
            for (int nf = 0; nf < 4; nf++) {
                const int col = tn * 128 + wn * 32 + nf * 8 + tc;
                float vx = c[mf][nf][half * 2 + 0];
                float vy = c[mf][nf][half * 2 + 1];
                if (bias) { vx += bias[col]; vy += bias[col + 1]; }
                if (col < N1) {
                    if (arow) { vx += arow[col]; vy += arow[col + 1]; }
                    if (relu) { vx = fmaxf(vx, 0.f); vy = fmaxf(vy, 0.f); }
                    if (c1row) *(float2*)(c1row + col) = make_float2(vx, vy);
                    if (ohr) {
                        const float sx = vx * oscale, sy = vy * oscale;
                        const bf16 bx = __float2bfloat16(sx);
                        const bf16 by = __float2bfloat16(sy);
                        *(ushort2*)((unsigned short*)ohr + col) =
                            make_ushort2(*(const unsigned short*)&bx, *(const unsigned short*)&by);
                        *(unsigned short*)(o8r + col) = cvt2_e4m3(sx * qs, sy * qs);
                        const float rx = (sx - __bfloat162float(bx)) * qs * 256.0f;
                        const float ry = (sy - __bfloat162float(by)) * qs * 256.0f;
                        *(unsigned short*)(orr + col) = cvt2_e4m3(rx, ry);
                    }
                } else {
                    *(float2*)(c2row + (col - N1)) = make_float2(vx, vy);
                }
            }
        }
    }
}

// ---------------- split fp32 -> bf16-hi + fp8-hi + fp8-res ----------------
__global__ void split_kernel(const float* __restrict__ s,
                             bf16* __restrict__ h, uint8_t* __restrict__ q8,
                             uint8_t* __restrict__ r8, float qs)
{
    const size_t i = (size_t)blockIdx.x * 256 + threadIdx.x;
    const float4 v = ((const float4*)s)[i];
    const bf16 b0 = __float2bfloat16(v.x), b1 = __float2bfloat16(v.y);
    const bf16 b2 = __float2bfloat16(v.z), b3 = __float2bfloat16(v.w);
    ((ushort4*)h)[i] = make_ushort4(*(const unsigned short*)&b0, *(const unsigned short*)&b1,
                                    *(const unsigned short*)&b2, *(const unsigned short*)&b3);
    const uint32_t qlo = cvt2_e4m3(v.x * qs, v.y * qs);
    const uint32_t qhi = cvt2_e4m3(v.z * qs, v.w * qs);
    ((uint32_t*)q8)[i] = qlo | (qhi << 16);
    const float rs = qs * 256.0f;
    const uint32_t rlo = cvt2_e4m3((v.x - __bfloat162float(b0)) * rs,
                                   (v.y - __bfloat162float(b1)) * rs);
    const uint32_t rhi = cvt2_e4m3((v.z - __bfloat162float(b2)) * rs,
                                   (v.w - __bfloat162float(b3)) * rs);
    ((uint32_t*)r8)[i] = rlo | (rhi << 16);
}

// transpose + split: WdcT[h,f] = Wdc[f,h]
__global__ void tsplit_kernel(const float* __restrict__ W,
                              bf16* __restrict__ th, uint8_t* __restrict__ t8,
                              uint8_t* __restrict__ tr, float qs)
{
    __shared__ float t[32][33];
    const int f0 = blockIdx.y * 32, h0 = blockIdx.x * 32;
    t[threadIdx.y][threadIdx.x] = W[(size_t)(f0 + threadIdx.y) * HH + h0 + threadIdx.x];
    __syncthreads();
    const float v = t[threadIdx.x][threadIdx.y];
    const bf16 b = __float2bfloat16(v);
    const size_t o = (size_t)(h0 + threadIdx.y) * FF + f0 + threadIdx.x;
    ((unsigned short*)th)[o] = *(const unsigned short*)&b;
    const unsigned short q = cvt2_e4m3(v * qs, 0.f);
    t8[o] = (uint8_t)(q & 0xFF);
    const unsigned short r = cvt2_e4m3((v - __bfloat162float(b)) * qs * 256.0f, 0.f);
    tr[o] = (uint8_t)(r & 0xFF);
}

// ---------------- LSTM pointwise ----------------
__global__ void lstm_kernel(const float* __restrict__ gates,
                            const float* __restrict__ cprev,
                            bf16* __restrict__ hh, uint8_t* __restrict__ h8,
                            uint8_t* __restrict__ hr8,
                            float* __restrict__ c, float* __restrict__ hf)
{
    const int idx = blockIdx.x * blockDim.x + threadIdx.x;
    const int n = idx >> 8;
    const int j4 = idx & 255;
    const float4* gp = (const float4*)(gates + (size_t)n * G4);
    const float4 gi = gp[j4];
    const float4 gf = gp[256 + j4];
    const float4 gg = gp[512 + j4];
    const float4 go = gp[768 + j4];
    float4 cp = make_float4(0.f, 0.f, 0.f, 0.f);
    if (cprev) cp = ((const float4*)cprev)[idx];
    float4 cn, hn;
    cn.x = sigm(gf.x) * cp.x + sigm(gi.x) * tanhf(gg.x);  hn.x = sigm(go.x) * tanhf(cn.x);
    cn.y = sigm(gf.y) * cp.y + sigm(gi.y) * tanhf(gg.y);  hn.y = sigm(go.y) * tanhf(cn.y);
    cn.z = sigm(gf.z) * cp.z + sigm(gi.z) * tanhf(gg.z);  hn.z = sigm(go.z) * tanhf(cn.z);
    cn.w = sigm(gf.w) * cp.w + sigm(gi.w) * tanhf(gg.w);  hn.w = sigm(go.w) * tanhf(cn.w);
    ((float4*)c)[idx] = cn;
    const bf16 b0 = __float2bfloat16(hn.x), b1 = __float2bfloat16(hn.y);
    const bf16 b2 = __float2bfloat16(hn.z), b3 = __float2bfloat16(hn.w);
    ((ushort4*)hh)[idx] = make_ushort4(*(const unsigned short*)&b0, *(const unsigned short*)&b1,
                                       *(const unsigned short*)&b2, *(const unsigned short*)&b3);
    const float qs = QS_ACT, rs = QS_ACT * 256.0f;
    const uint32_t qlo = cvt2_e4m3(hn.x * qs, hn.y * qs);
    const uint32_t qhi = cvt2_e4m3(hn.z * qs, hn.w * qs);
    ((uint32_t*)h8)[idx] = qlo | (qhi << 16);
    const uint32_t rlo = cvt2_e4m3((hn.x - __bfloat162float(b0)) * rs,
                                   (hn.y - __bfloat162float(b1)) * rs);
    const uint32_t rhi = cvt2_e4m3((hn.z - __bfloat162float(b2)) * rs,
                                   (hn.w - __bfloat162float(b3)) * rs);
    ((uint32_t*)hr8)[idx] = rlo | (rhi << 16);
    if (hf) ((float4*)hf)[idx] = hn;
}

// ---------------- bias prep ----------------
__global__ void prep_kernel(const float* __restrict__ dWih, const float* __restrict__ bdc,
                            const float* __restrict__ dbih, const float* __restrict__ dbhh,
                            const float* __restrict__ ebih, const float* __restrict__ ebhh,
                            float* __restrict__ bdec0, float* __restrict__ bcat,
                            float* __restrict__ benc)
{
    const int g = blockIdx.x;       // 0..NCAT-1
    const int t = threadIdx.x;      // 128
    if (g >= G4) {
        if (t == 0) bcat[g] = bdc[g - G4];
        return;
    }
    float p = 0.f;
    for (int k = t; k < FF; k += 128) p += dWih[(size_t)g * FF + k] * bdc[k];
    p += __shfl_down_sync(0xffffffffu, p, 16);
    p += __shfl_down_sync(0xffffffffu, p, 8);
    p += __shfl_down_sync(0xffffffffu, p, 4);
    p += __shfl_down_sync(0xffffffffu, p, 2);
    p += __shfl_down_sync(0xffffffffu, p, 1);
    __shared__ float sred[4];
    if ((t & 31) == 0) sred[t >> 5] = p;
    __syncthreads();
    if (t == 0) {
        const float srow = sred[0] + sred[1] + sred[2] + sred[3];
        const float b0 = dbih[g] + dbhh[g];
        bdec0[g] = b0;
        bcat[g] = b0 + srow;
        benc[g] = ebih[g] + ebhh[g];
    }
}

// ---------------- skinny head ----------------
__global__ void encscore_kernel(const float* __restrict__ h, const float* __restrict__ Wec,
                                const float* __restrict__ bec, float* __restrict__ out)
{
    const int warp = threadIdx.x >> 5;
    const int lane = threadIdx.x & 31;
    const int r = blockIdx.x * 8 + warp;
    float acc[CC];
#pragma unroll
    for (int n = 0; n < CC; n++) acc[n] = 0.f;
    const float* hr = h + (size_t)r * FF;
    for (int u = 0; u < FF / 32; u++) {
        const float hv = hr[u * 32 + lane];
#pragma unroll
        for (int n = 0; n < CC; n++) acc[n] += hv * Wec[n * FF + u * 32 + lane];
    }
#pragma unroll
    for (int n = 0; n < CC; n++) {
        float v = acc[n];
        v += __shfl_xor_sync(0xffffffffu, v, 16);
        v += __shfl_xor_sync(0xffffffffu, v, 8);
        v += __shfl_xor_sync(0xffffffffu, v, 4);
        v += __shfl_xor_sync(0xffffffffu, v, 2);
        v += __shfl_xor_sync(0xffffffffu, v, 1);
        if (lane == 0) out[(size_t)r * CC + n] = v + bec[n];
    }
}

// ---------------- launch ----------------
extern "C" void kernel_launch(void* const* d_in, const int* in_sizes, int n_in,
                              void* d_out, int out_size)
{
    const float* x    = (const float*)d_in[0];
    const float* Wf   = (const float*)d_in[1];
    const float* bf   = (const float*)d_in[2];
    const float* dWih = (const float*)d_in[3];
    const float* dWhh = (const float*)d_in[4];
    const float* dbih = (const float*)d_in[5];
    const float* dbhh = (const float*)d_in[6];
    const float* Wdc  = (const float*)d_in[7];
    const float* bdc  = (const float*)d_in[8];
    const float* eWih = (const float*)d_in[9];
    const float* eWhh = (const float*)d_in[10];
    const float* ebih = (const float*)d_in[11];
    const float* ebhh = (const float*)d_in[12];
    const float* Wec  = (const float*)d_in[13];
    const float* bec  = (const float*)d_in[14];

    float* enc_out = (float*)d_out;
    float* dec_out = (float*)d_out + (size_t)NROW * CC;

    unsigned char* ar = nullptr;
    cudaGetSymbolAddress((void**)&ar, g_arena);

    bf16*    xh  = (bf16*)(ar + O_XH);
    uint8_t* x8  = ar + O_X8;   uint8_t* xr  = ar + O_XR;
    bf16*    Wfh = (bf16*)(ar + O_WFH);
    uint8_t* Wf8 = ar + O_WF8;  uint8_t* Wfr = ar + O_WFR;
    bf16*    dih = (bf16*)(ar + O_DIH);
    uint8_t* di8 = ar + O_DI8;  uint8_t* dir = ar + O_DIR;
    bf16*    eih = (bf16*)(ar + O_EIH);
    uint8_t* ei8 = ar + O_EI8;  uint8_t* eir = ar + O_EIR;
    bf16*    ehh = (bf16*)(ar + O_EHH);
    uint8_t* eh8 = ar + O_EH8;  uint8_t* ehr = ar + O_EHR;
    bf16*    wth = (bf16*)(ar + O_WTH);
    uint8_t* wt8 = ar + O_WT8;  uint8_t* wtr = ar + O_WTR;
    bf16*    wch = (bf16*)(ar + O_WCH);
    uint8_t* wc8 = ar + O_WC8;  uint8_t* wcr = ar + O_WCR;
    bf16*    wdh = wch + (size_t)G4 * HH;
    uint8_t* wd8 = wc8 + (size_t)G4 * HH;
    uint8_t* wdr = wcr + (size_t)G4 * HH;
    bf16*    fh  = (bf16*)(ar + O_FH);
    uint8_t* f8  = ar + O_F8;   uint8_t* fr  = ar + O_FR;
    bf16*    hhp = (bf16*)(ar + O_HHO);
    uint8_t* h8  = ar + O_H8;   uint8_t* hr  = ar + O_HR;
    bf16*    lh  = (bf16*)(ar + O_LH);
    uint8_t* l8  = ar + O_L8;   uint8_t* lr  = ar + O_LR;
    float* cbuf  = (float*)(ar + O_C);
    float* gates = (float*)(ar + O_G);
    float* hfbuf = (float*)(ar + O_HF);
    float* bdec0 = (float*)(ar + O_B0);
    float* bcat  = (float*)(ar + O_B1);
    float* benc  = (float*)(ar + O_B2);

    cudaFuncSetAttribute(tcgemm, cudaFuncAttributeMaxDynamicSharedMemorySize, SMEM_DYN);

    // preprocessing
    split_kernel<<<EX / 1024, 256>>>(x, xh, x8, xr, QS_ACT);
    split_kernel<<<EW4 / 1024, 256>>>(Wf, Wfh, Wf8, Wfr, QS_WGT);
    split_kernel<<<EW4 / 1024, 256>>>(dWih, dih, di8, dir, QS_WGT);
    split_kernel<<<EW4 / 1024, 256>>>(eWih, eih, ei8, eir, QS_WGT);
    split_kernel<<<EW4 / 1024, 256>>>(eWhh, ehh, eh8, ehr, QS_WGT);
    split_kernel<<<EW1 / 1024, 256>>>(Wdc, wdh, wd8, wdr, QS_WGT);
    tsplit_kernel<<<dim3(HH / 32, FF / 32), dim3(32, 32)>>>(Wdc, wth, wt8, wtr, QS_WGT);
    prep_kernel<<<NCAT, 128>>>(dWih, bdc, dbih, dbhh, ebih, ebhh, bdec0, bcat, benc);

    const dim3 gBig(G4 / 128, NROW / 128);    // 32 x 32
    const dim3 gOut(FF / 128, NROW / 128);    // 8 x 32
    const dim3 gFuse(NCAT / 128, NROW / 128); // 40 x 32
    const dim3 gWc(FF / 128, G4 / 128);       // 8 x 32
    const int  lstmGrid = NROW * HH / 4 / 256;

    PassCfg P;

    // 1) feats = relu(x @ Wf^T + bf) -> fh/f8/fr (qs 16)
    P.a8[0] = xr; P.b8[0] = Wf8;  P.a8[1] = x8; P.b8[1] = Wfr;  P.n8 = 2;
    P.ah[0] = xh; P.bh[0] = Wfh;  P.nh = 1;
    tcgemm<<<gOut, 256, SMEM_DYN>>>(P, INN, FF, RS_AW, bf, nullptr, 0,
                                    nullptr, 0, nullptr, 0,
                                    fh, f8, fr, FF, 1.0f, QS_ACT, 1);

    // 2) Wcomb = dWih @ Wdc + dWhh -> wch/wc8/wcr rows 0..4095 (qs 512)
    P.a8[0] = dir; P.b8[0] = wt8;  P.a8[1] = di8; P.b8[1] = wtr;  P.n8 = 2;
    P.ah[0] = dih; P.bh[0] = wth;  P.nh = 1;
    tcgemm<<<gWc, 256, SMEM_DYN>>>(P, FF, FF, RS_WW, nullptr, dWhh, HH,
                                   nullptr, 0, nullptr, 0,
                                   wch, wc8, wcr, HH, 1.0f, QS_WGT, 0);

    // 3) decoder step 0: gates = feats @ dWih^T + bdec0
    P.a8[0] = fr; P.b8[0] = di8;  P.a8[1] = f8; P.b8[1] = dir;  P.n8 = 2;
    P.ah[0] = fh; P.bh[0] = dih;  P.nh = 1;
    tcgemm<<<gBig, 256, SMEM_DYN>>>(P, FF, G4, RS_AW, bdec0, nullptr, 0,
                                    gates, G4, nullptr, 0,
                                    nullptr, nullptr, nullptr, 0, 1.0f, 0.f, 0);
    lstm_kernel<<<lstmGrid, 256>>>(gates, nullptr, hhp, h8, hr, cbuf, nullptr);

    // 4) fused decoder steps: [gates_{t+1} | out_t] = h_t @ [Wcomb ; Wdc]^T + bcat
    for (int t = 0; t < DD - 1; t++) {
        P.a8[0] = hr; P.b8[0] = wc8;  P.a8[1] = h8; P.b8[1] = wcr;  P.n8 = 2;
        P.ah[0] = hhp; P.bh[0] = wch; P.nh = 1;
        tcgemm<<<gFuse, 256, SMEM_DYN>>>(P, HH, G4, RS_AW, bcat, nullptr, 0,
                                         gates, G4, dec_out + (size_t)t * FF, DD * FF,
                                         nullptr, nullptr, nullptr, 0, 1.0f, 0.f, 0);
        lstm_kernel<<<lstmGrid, 256>>>(gates, cbuf, hhp, h8, hr, cbuf, nullptr);
    }

    // 5) out_7 = h_7 @ Wdc^T + bdc ; also emits (v/D) split for encoder h0
    P.a8[0] = hr; P.b8[0] = wd8;  P.a8[1] = h8; P.b8[1] = wdr;  P.n8 = 2;
    P.ah[0] = hhp; P.bh[0] = wdh; P.nh = 1;
    tcgemm<<<gOut, 256, SMEM_DYN>>>(P, HH, FF, RS_AW, bdc, nullptr, 0,
                                    dec_out + (size_t)(DD - 1) * FF, DD * FF, nullptr, 0,
                                    lh, l8, lr, FF, 1.0f / (float)DD, QS_ACT, 0);

    // 6) encoder gates = feats @ eWih^T + (last/D) @ eWhh^T + benc
    P.a8[0] = fr; P.b8[0] = ei8;  P.a8[1] = f8; P.b8[1] = eir;
    P.a8[2] = lr; P.b8[2] = eh8;  P.a8[3] = l8; P.b8[3] = ehr;  P.n8 = 4;
    P.ah[0] = fh; P.bh[0] = eih;  P.ah[1] = lh; P.bh[1] = ehh;  P.nh = 2;
    tcgemm<<<gBig, 256, SMEM_DYN>>>(P, FF, G4, RS_AW, benc, nullptr, 0,
                                    gates, G4, nullptr, 0,
                                    nullptr, nullptr, nullptr, 0, 1.0f, 0.f, 0);
    lstm_kernel<<<lstmGrid, 256>>>(gates, nullptr, hhp, h8, hr, cbuf, hfbuf);

    encscore_kernel<<<NROW / 8, 256>>>(hfbuf, Wec, bec, enc_out);
}

// round 17
// speedup vs baseline: 1.2736x; 1.2736x over previous
#include <cuda_runtime.h>
#include <cuda_bf16.h>
#include <cuda_fp16.h>
#include <math.h>
#include <stdint.h>

#define DD   8
#define FF   1024
#define HH   1024
#define CC   22
#define INN  4096
#define NROW 4096
#define G4   4096
#define NCAT (G4 + FF)    // 5120

typedef __nv_bfloat16 bf16;

constexpr size_t EX  = (size_t)NROW * INN;
constexpr size_t EW4 = (size_t)G4 * FF;
constexpr size_t EW1 = (size_t)FF * HH;
constexpr size_t EWC = (size_t)NCAT * HH;
constexpr size_t EH  = (size_t)NROW * HH;

// ---------------- arena ----------------
constexpr size_t O_XH  = 0;                    // bf16 pairs (2B each half)
constexpr size_t O_XL  = O_XH  + 2 * EX;
constexpr size_t O_WFH = O_XL  + 2 * EX;
constexpr size_t O_WFL = O_WFH + 2 * EW4;
constexpr size_t O_DIH = O_WFL + 2 * EW4;
constexpr size_t O_DIL = O_DIH + 2 * EW4;
constexpr size_t O_WTH = O_DIL + 2 * EW4;
constexpr size_t O_WTL = O_WTH + 2 * EW1;
constexpr size_t O_WCH = O_WTL + 2 * EW1;      // [NCAT,HH] bf16: Wcomb rows 0..4095, Wdc rows 4096..
constexpr size_t O_WCL = O_WCH + 2 * EWC;
constexpr size_t O_FH  = O_WCL + 2 * EWC;
constexpr size_t O_FL  = O_FH  + 2 * EW4;
constexpr size_t O_HHB = O_FL  + 2 * EW4;      // h bf16 pair
constexpr size_t O_HLB = O_HHB + 2 * EH;
// fp16 operands
constexpr size_t O_F6H = O_HLB + 2 * EH;       // feats fp16 hi
constexpr size_t O_F6R = O_F6H + 2 * EW4;      // feats fp16 res
constexpr size_t O_H6H = O_F6R + 2 * EW4;      // h fp16 hi
constexpr size_t O_H6R = O_H6H + 2 * EH;       // h fp16 res
constexpr size_t O_L6H = O_H6R + 2 * EH;       // (last/D) fp16 hi
constexpr size_t O_L6R = O_L6H + 2 * EH;       // (last/D) fp16 res
constexpr size_t O_EI6 = O_L6R + 2 * EH;       // eWih fp16 hi
constexpr size_t O_EH6 = O_EI6 + 2 * EW4;      // eWhh fp16 hi
constexpr size_t O_WD6 = O_EH6 + 2 * EW4;      // Wdc fp16 hi
constexpr size_t O_C   = O_WD6 + 2 * EW1;
constexpr size_t O_G   = O_C   + 4 * EH;
constexpr size_t O_HF  = O_G   + 4 * (size_t)NROW * G4;
constexpr size_t O_B0  = O_HF  + 4 * EH;
constexpr size_t O_B1  = O_B0  + 4 * (size_t)G4;
constexpr size_t O_B2  = O_B1  + 4 * (size_t)NCAT;
constexpr size_t ARENA = O_B2  + 4 * (size_t)G4;

__device__ __align__(1024) unsigned char g_arena[ARENA];

// ---------------- helpers ----------------
__device__ __forceinline__ uint32_t smem_u32(const void* p) {
    uint32_t a;
    asm("{ .reg .u64 t; cvta.to.shared.u64 t, %1; cvt.u32.u64 %0, t; }" : "=r"(a) : "l"(p));
    return a;
}
__device__ __forceinline__ void ldsm4(uint32_t& r0, uint32_t& r1, uint32_t& r2, uint32_t& r3,
                                      uint32_t addr) {
    asm volatile("ldmatrix.sync.aligned.m8n8.x4.shared.b16 {%0,%1,%2,%3}, [%4];"
                 : "=r"(r0), "=r"(r1), "=r"(r2), "=r"(r3) : "r"(addr));
}
template<int HALF>
__device__ __forceinline__ void mma16816(float* c, const uint32_t* a, const uint32_t* b) {
    if (HALF)
        asm volatile("mma.sync.aligned.m16n8k16.row.col.f32.f16.f16.f32 "
                     "{%0,%1,%2,%3}, {%4,%5,%6,%7}, {%8,%9}, {%0,%1,%2,%3};"
                     : "+f"(c[0]), "+f"(c[1]), "+f"(c[2]), "+f"(c[3])
                     : "r"(a[0]), "r"(a[1]), "r"(a[2]), "r"(a[3]), "r"(b[0]), "r"(b[1]));
    else
        asm volatile("mma.sync.aligned.m16n8k16.row.col.f32.bf16.bf16.f32 "
                     "{%0,%1,%2,%3}, {%4,%5,%6,%7}, {%8,%9}, {%0,%1,%2,%3};"
                     : "+f"(c[0]), "+f"(c[1]), "+f"(c[2]), "+f"(c[3])
                     : "r"(a[0]), "r"(a[1]), "r"(a[2]), "r"(a[3]), "r"(b[0]), "r"(b[1]));
}
__device__ __forceinline__ void split2(float v, unsigned short& hi, unsigned short& lo) {
    bf16 h = __float2bfloat16(v);
    bf16 l = __float2bfloat16(v - __bfloat162float(h));
    hi = *(unsigned short*)&h;
    lo = *(unsigned short*)&l;
}
__device__ __forceinline__ void split2h(float v, unsigned short& hi, unsigned short& lo) {
    __half h = __float2half_rn(v);
    __half l = __float2half_rn(v - __half2float(h));
    hi = *(unsigned short*)&h;
    lo = *(unsigned short*)&l;
}
__device__ __forceinline__ float sigm(float x) { return 1.0f / (1.0f + expf(-x)); }

// ---------------- GEMM (CTA 128x128, warp 64x32, 2 CTA/SM, BK=32; proven R15 mainloop) ----------------
// C[M,N] = sum_passes (A0_p + A1_p) @ B_p^T; dual passes share B fragments.
// HALF=1 -> fp16 operands / mma; HALF=0 -> bf16.
// Epilogue: cols < N1 -> C1 (+bias, +Cadd, relu, optional bf16 split pair, optional fp16 split pair
//           of v*oscale); cols >= N1 -> C2 (+bias only) at col-N1.
struct PassSpec { const uint16_t* A0; const uint16_t* A1; const uint16_t* B; };
struct Passes4 { PassSpec p[4]; };

#define STAGES      3
#define ROWPITCH    80
#define TILE_BYTES  (128 * ROWPITCH)    // 10240
#define STAGE_BYTES (3 * TILE_BYTES)    // 30720: [A0 | A1 | B]
#define SMEM_DYN    (STAGES * STAGE_BYTES)  // 92160

template<int HALF>
__global__ __launch_bounds__(256, 2)
void tcgemm(Passes4 P, int nP, int Kp, int N1,
            const float* __restrict__ bias,
            const float* __restrict__ Cadd, int ldadd,
            float* __restrict__ C1, int ldc1,
            float* __restrict__ C2, int ldc2,
            uint16_t* __restrict__ Obh, uint16_t* __restrict__ Obl,
            uint16_t* __restrict__ Ohh, uint16_t* __restrict__ Ohr,
            int ldo, float oscale, int relu)
{
    extern __shared__ __align__(16) unsigned char dsm[];
    const uint32_t sbase = smem_u32(dsm);

    const int tid = threadIdx.x, wid = tid >> 5, lane = tid & 31;
    const int wm = wid >> 2;
    const int wn = wid & 3;
    const int tm = blockIdx.y, tn = blockIdx.x;

    const int ck  = Kp >> 5;
    const int nkt = nP * ck;

    int lp = 0, lkk = 0, lbuf = 0;
    auto issue_load = [&]() {
        if (lp >= nP) return;
        const PassSpec ps = P.p[lp];
        const int ko = lkk << 5;
        const uint16_t* A0g = ps.A0 + (size_t)(tm * 128) * Kp + ko;
        const uint16_t* Bg  = ps.B  + (size_t)(tn * 128) * Kp + ko;
        const uint32_t s0 = sbase + (uint32_t)lbuf * STAGE_BYTES;
        const uint32_t sB = s0 + 2 * TILE_BYTES;
#pragma unroll
        for (int j = 0; j < 2; j++) {
            const int i = tid + 256 * j;
            const int row = i >> 2, ch = i & 3;
            const uint32_t d = (uint32_t)row * ROWPITCH + (uint32_t)ch * 16;
            asm volatile("cp.async.cg.shared.global [%0], [%1], 16;"
                         :: "r"(s0 + d), "l"(A0g + (size_t)row * Kp + ch * 8) : "memory");
            asm volatile("cp.async.cg.shared.global [%0], [%1], 16;"
                         :: "r"(sB + d), "l"(Bg + (size_t)row * Kp + ch * 8) : "memory");
        }
        if (ps.A1) {
            const uint16_t* A1g = ps.A1 + (size_t)(tm * 128) * Kp + ko;
            const uint32_t s1 = s0 + TILE_BYTES;
#pragma unroll
            for (int j = 0; j < 2; j++) {
                const int i = tid + 256 * j;
                const int row = i >> 2, ch = i & 3;
                const uint32_t d = (uint32_t)row * ROWPITCH + (uint32_t)ch * 16;
                asm volatile("cp.async.cg.shared.global [%0], [%1], 16;"
                             :: "r"(s1 + d), "l"(A1g + (size_t)row * Kp + ch * 8) : "memory");
            }
        }
        asm volatile("cp.async.commit_group;" ::: "memory");
        lkk++; if (lkk == ck) { lkk = 0; lp++; }
        lbuf++; if (lbuf == STAGES) lbuf = 0;
    };

    float c[4][4][4];
#pragma unroll
    for (int i = 0; i < 4; i++)
#pragma unroll
        for (int j = 0; j < 4; j++)
#pragma unroll
            for (int k = 0; k < 4; k++) c[i][j][k] = 0.f;

    const uint32_t a_row = (uint32_t)(wm * 64 + (lane & 15));
    const uint32_t a_ch  = (uint32_t)((lane >> 4) * 16);
    const uint32_t b_row = (uint32_t)(wn * 32 + ((lane >> 4) << 3) + (lane & 7));
    const uint32_t b_ch  = (uint32_t)(((lane >> 3) & 1) * 16);

    issue_load();
    issue_load();

    int cbuf = 0, done = 0;
    for (int p = 0; p < nP; p++) {
        const bool dual = (P.p[p].A1 != nullptr);
        for (int kk = 0; kk < ck; kk++) {
            done++;
            if (done < nkt) asm volatile("cp.async.wait_group 1;" ::: "memory");
            else            asm volatile("cp.async.wait_group 0;" ::: "memory");
            __syncthreads();

            issue_load();

            const uint32_t s0 = sbase + (uint32_t)cbuf * STAGE_BYTES;
            const uint32_t s1 = s0 + TILE_BYTES;
            const uint32_t sB = s0 + 2 * TILE_BYTES;
            cbuf++; if (cbuf == STAGES) cbuf = 0;
#pragma unroll
            for (int ks = 0; ks < 2; ks++) {
                uint32_t a[4][4], b[4][2];
#pragma unroll
                for (int np = 0; np < 2; np++) {
                    const uint32_t addr = sB + (b_row + np * 16) * ROWPITCH + ks * 32 + b_ch;
                    ldsm4(b[2 * np][0], b[2 * np][1], b[2 * np + 1][0], b[2 * np + 1][1], addr);
                }
#pragma unroll
                for (int mf = 0; mf < 4; mf++) {
                    const uint32_t addr = s0 + (a_row + mf * 16) * ROWPITCH + ks * 32 + a_ch;
                    ldsm4(a[mf][0], a[mf][1], a[mf][2], a[mf][3], addr);
                }
#pragma unroll
                for (int mf = 0; mf < 4; mf++)
#pragma unroll
                    for (int nf = 0; nf < 4; nf++)
                        mma16816<HALF>(c[mf][nf], a[mf], b[nf]);
                if (dual) {
#pragma unroll
                    for (int mf = 0; mf < 4; mf++) {
                        const uint32_t addr = s1 + (a_row + mf * 16) * ROWPITCH + ks * 32 + a_ch;
                        ldsm4(a[mf][0], a[mf][1], a[mf][2], a[mf][3], addr);
                    }
#pragma unroll
                    for (int mf = 0; mf < 4; mf++)
#pragma unroll
                        for (int nf = 0; nf < 4; nf++)
                            mma16816<HALF>(c[mf][nf], a[mf], b[nf]);
                }
            }
        }
    }

    // ---------------- epilogue ----------------
    const int tr = lane >> 2, tc = (lane & 3) * 2;
#pragma unroll
    for (int mf = 0; mf < 4; mf++) {
#pragma unroll
        for (int half = 0; half < 2; half++) {
            const size_t row = (size_t)tm * 128 + wm * 64 + mf * 16 + tr + half * 8;
            float* c1row = C1 ? C1 + row * (size_t)ldc1 : (float*)0;
            float* c2row = C2 ? C2 + row * (size_t)ldc2 : (float*)0;
            const float* arow = Cadd ? Cadd + row * (size_t)ldadd : (const float*)0;
            uint16_t* obh = Obh ? Obh + row * (size_t)ldo : (uint16_t*)0;
            uint16_t* obl = Obl ? Obl + row * (size_t)ldo : (uint16_t*)0;
            uint16_t* ohh = Ohh ? Ohh + row * (size_t)ldo : (uint16_t*)0;
            uint16_t* ohr = Ohr ? Ohr + row * (size_t)ldo : (uint16_t*)0;
#pragma unroll
            for (int nf = 0; nf < 4; nf++) {
                const int col = tn * 128 + wn * 32 + nf * 8 + tc;
                float vx = c[mf][nf][half * 2 + 0];
                float vy = c[mf][nf][half * 2 + 1];
                if (bias) { vx += bias[col]; vy += bias[col + 1]; }
                if (col < N1) {
                    if (arow) { vx += arow[col]; vy += arow[col + 1]; }
                    if (relu) { vx = fmaxf(vx, 0.f); vy = fmaxf(vy, 0.f); }
                    if (c1row) *(float2*)(c1row + col) = make_float2(vx, vy);
                    const float sx = vx * oscale, sy = vy * oscale;
                    if (obh) {
                        unsigned short h0, l0, h1, l1;
                        split2(sx, h0, l0);
                        split2(sy, h1, l1);
                        *(ushort2*)(obh + col) = make_ushort2(h0, h1);
                        *(ushort2*)(obl + col) = make_ushort2(l0, l1);
                    }
                    if (ohh) {
                        unsigned short h0, l0, h1, l1;
                        split2h(sx, h0, l0);
                        split2h(sy, h1, l1);
                        *(ushort2*)(ohh + col) = make_ushort2(h0, h1);
                        *(ushort2*)(ohr + col) = make_ushort2(l0, l1);
                    }
                } else {
                    *(float2*)(c2row + (col - N1)) = make_float2(vx, vy);
                }
            }
        }
    }
}

// ---------------- splits ----------------
__global__ void split_kernel(const float* __restrict__ s,
                             uint16_t* __restrict__ h, uint16_t* __restrict__ l)
{
    const size_t i = (size_t)blockIdx.x * 256 + threadIdx.x;
    const float4 v = ((const float4*)s)[i];
    unsigned short h0, l0, h1, l1, h2, l2, h3, l3;
    split2(v.x, h0, l0); split2(v.y, h1, l1); split2(v.z, h2, l2); split2(v.w, h3, l3);
    ((ushort4*)h)[i] = make_ushort4(h0, h1, h2, h3);
    ((ushort4*)l)[i] = make_ushort4(l0, l1, l2, l3);
}

// fp16 hi-only convert
__global__ void cvt16_kernel(const float* __restrict__ s, uint16_t* __restrict__ h)
{
    const size_t i = (size_t)blockIdx.x * 256 + threadIdx.x;
    const float4 v = ((const float4*)s)[i];
    const __half a = __float2half_rn(v.x), b = __float2half_rn(v.y);
    const __half c = __float2half_rn(v.z), d = __float2half_rn(v.w);
    ((ushort4*)h)[i] = make_ushort4(*(const unsigned short*)&a, *(const unsigned short*)&b,
                                    *(const unsigned short*)&c, *(const unsigned short*)&d);
}

// transpose + bf16 split: WdcT[h,f] = Wdc[f,h]
__global__ void tsplit_kernel(const float* __restrict__ W,
                              uint16_t* __restrict__ th, uint16_t* __restrict__ tl)
{
    __shared__ float t[32][33];
    const int f0 = blockIdx.y * 32, h0 = blockIdx.x * 32;
    t[threadIdx.y][threadIdx.x] = W[(size_t)(f0 + threadIdx.y) * HH + h0 + threadIdx.x];
    __syncthreads();
    const float v = t[threadIdx.x][threadIdx.y];
    unsigned short hi, lo;
    split2(v, hi, lo);
    const size_t o = (size_t)(h0 + threadIdx.y) * FF + f0 + threadIdx.x;
    th[o] = hi;
    tl[o] = lo;
}

// ---------------- LSTM pointwise (emits bf16 pair + fp16 pair) ----------------
__global__ void lstm_kernel(const float* __restrict__ gates,
                            const float* __restrict__ cprev,
                            uint16_t* __restrict__ hh, uint16_t* __restrict__ hl,
                            uint16_t* __restrict__ h6h, uint16_t* __restrict__ h6r,
                            float* __restrict__ c, float* __restrict__ hf)
{
    const int idx = blockIdx.x * blockDim.x + threadIdx.x;
    const int n = idx >> 8;
    const int j4 = idx & 255;
    const float4* gp = (const float4*)(gates + (size_t)n * G4);
    const float4 gi = gp[j4];
    const float4 gf = gp[256 + j4];
    const float4 gg = gp[512 + j4];
    const float4 go = gp[768 + j4];
    float4 cp = make_float4(0.f, 0.f, 0.f, 0.f);
    if (cprev) cp = ((const float4*)cprev)[idx];
    float4 cn, hn;
    cn.x = sigm(gf.x) * cp.x + sigm(gi.x) * tanhf(gg.x);  hn.x = sigm(go.x) * tanhf(cn.x);
    cn.y = sigm(gf.y) * cp.y + sigm(gi.y) * tanhf(gg.y);  hn.y = sigm(go.y) * tanhf(cn.y);
    cn.z = sigm(gf.z) * cp.z + sigm(gi.z) * tanhf(gg.z);  hn.z = sigm(go.z) * tanhf(cn.z);
    cn.w = sigm(gf.w) * cp.w + sigm(gi.w) * tanhf(gg.w);  hn.w = sigm(go.w) * tanhf(cn.w);
    ((float4*)c)[idx] = cn;
    unsigned short h0, l0, h1, l1, h2, l2, h3, l3;
    split2(hn.x, h0, l0); split2(hn.y, h1, l1); split2(hn.z, h2, l2); split2(hn.w, h3, l3);
    ((ushort4*)hh)[idx] = make_ushort4(h0, h1, h2, h3);
    ((ushort4*)hl)[idx] = make_ushort4(l0, l1, l2, l3);
    split2h(hn.x, h0, l0); split2h(hn.y, h1, l1); split2h(hn.z, h2, l2); split2h(hn.w, h3, l3);
    ((ushort4*)h6h)[idx] = make_ushort4(h0, h1, h2, h3);
    ((ushort4*)h6r)[idx] = make_ushort4(l0, l1, l2, l3);
    if (hf) ((float4*)hf)[idx] = hn;
}

// ---------------- bias prep ----------------
__global__ void prep_kernel(const float* __restrict__ dWih, const float* __restrict__ bdc,
                            const float* __restrict__ dbih, const float* __restrict__ dbhh,
                            const float* __restrict__ ebih, const float* __restrict__ ebhh,
                            float* __restrict__ bdec0, float* __restrict__ bcat,
                            float* __restrict__ benc)
{
    const int g = blockIdx.x;
    const int t = threadIdx.x;
    if (g >= G4) {
        if (t == 0) bcat[g] = bdc[g - G4];
        return;
    }
    float p = 0.f;
    for (int k = t; k < FF; k += 128) p += dWih[(size_t)g * FF + k] * bdc[k];
    p += __shfl_down_sync(0xffffffffu, p, 16);
    p += __shfl_down_sync(0xffffffffu, p, 8);
    p += __shfl_down_sync(0xffffffffu, p, 4);
    p += __shfl_down_sync(0xffffffffu, p, 2);
    p += __shfl_down_sync(0xffffffffu, p, 1);
    __shared__ float sred[4];
    if ((t & 31) == 0) sred[t >> 5] = p;
    __syncthreads();
    if (t == 0) {
        const float srow = sred[0] + sred[1] + sred[2] + sred[3];
        const float b0 = dbih[g] + dbhh[g];
        bdec0[g] = b0;
        bcat[g] = b0 + srow;
        benc[g] = ebih[g] + ebhh[g];
    }
}

// ---------------- skinny head ----------------
__global__ void encscore_kernel(const float* __restrict__ h, const float* __restrict__ Wec,
                                const float* __restrict__ bec, float* __restrict__ out)
{
    const int warp = threadIdx.x >> 5;
    const int lane = threadIdx.x & 31;
    const int r = blockIdx.x * 8 + warp;
    float acc[CC];
#pragma unroll
    for (int n = 0; n < CC; n++) acc[n] = 0.f;
    const float* hr = h + (size_t)r * FF;
    for (int u = 0; u < FF / 32; u++) {
        const float hv = hr[u * 32 + lane];
#pragma unroll
        for (int n = 0; n < CC; n++) acc[n] += hv * Wec[n * FF + u * 32 + lane];
    }
#pragma unroll
    for (int n = 0; n < CC; n++) {
        float v = acc[n];
        v += __shfl_xor_sync(0xffffffffu, v, 16);
        v += __shfl_xor_sync(0xffffffffu, v, 8);
        v += __shfl_xor_sync(0xffffffffu, v, 4);
        v += __shfl_xor_sync(0xffffffffu, v, 2);
        v += __shfl_xor_sync(0xffffffffu, v, 1);
        if (lane == 0) out[(size_t)r * CC + n] = v + bec[n];
    }
}

// ---------------- launch ----------------
extern "C" void kernel_launch(void* const* d_in, const int* in_sizes, int n_in,
                              void* d_out, int out_size)
{
    const float* x    = (const float*)d_in[0];
    const float* Wf   = (const float*)d_in[1];
    const float* bf   = (const float*)d_in[2];
    const float* dWih = (const float*)d_in[3];
    const float* dWhh = (const float*)d_in[4];
    const float* dbih = (const float*)d_in[5];
    const float* dbhh = (const float*)d_in[6];
    const float* Wdc  = (const float*)d_in[7];
    const float* bdc  = (const float*)d_in[8];
    const float* eWih = (const float*)d_in[9];
    const float* eWhh = (const float*)d_in[10];
    const float* ebih = (const float*)d_in[11];
    const float* ebhh = (const float*)d_in[12];
    const float* Wec  = (const float*)d_in[13];
    const float* bec  = (const float*)d_in[14];

    float* enc_out = (float*)d_out;
    float* dec_out = (float*)d_out + (size_t)NROW * CC;

    unsigned char* ar = nullptr;
    cudaGetSymbolAddress((void**)&ar, g_arena);

    uint16_t* xh  = (uint16_t*)(ar + O_XH);   uint16_t* xl  = (uint16_t*)(ar + O_XL);
    uint16_t* Wfh = (uint16_t*)(ar + O_WFH);  uint16_t* Wfl = (uint16_t*)(ar + O_WFL);
    uint16_t* dih = (uint16_t*)(ar + O_DIH);  uint16_t* dil = (uint16_t*)(ar + O_DIL);
    uint16_t* wth = (uint16_t*)(ar + O_WTH);  uint16_t* wtl = (uint16_t*)(ar + O_WTL);
    uint16_t* wch = (uint16_t*)(ar + O_WCH);  uint16_t* wcl = (uint16_t*)(ar + O_WCL);
    uint16_t* wdh = wch + (size_t)G4 * HH;    // Wdc bf16 split = rows 4096..5119
    uint16_t* wdl = wcl + (size_t)G4 * HH;
    uint16_t* fh  = (uint16_t*)(ar + O_FH);   uint16_t* fl  = (uint16_t*)(ar + O_FL);
    uint16_t* hh  = (uint16_t*)(ar + O_HHB);  uint16_t* hl  = (uint16_t*)(ar + O_HLB);
    uint16_t* f6h = (uint16_t*)(ar + O_F6H);  uint16_t* f6r = (uint16_t*)(ar + O_F6R);
    uint16_t* h6h = (uint16_t*)(ar + O_H6H);  uint16_t* h6r = (uint16_t*)(ar + O_H6R);
    uint16_t* l6h = (uint16_t*)(ar + O_L6H);  uint16_t* l6r = (uint16_t*)(ar + O_L6R);
    uint16_t* ei6 = (uint16_t*)(ar + O_EI6);
    uint16_t* eh6 = (uint16_t*)(ar + O_EH6);
    uint16_t* wd6 = (uint16_t*)(ar + O_WD6);
    float* cbuf  = (float*)(ar + O_C);
    float* gates = (float*)(ar + O_G);
    float* hfbuf = (float*)(ar + O_HF);
    float* bdec0 = (float*)(ar + O_B0);
    float* bcat  = (float*)(ar + O_B1);
    float* benc  = (float*)(ar + O_B2);

    cudaFuncSetAttribute(tcgemm<0>, cudaFuncAttributeMaxDynamicSharedMemorySize, SMEM_DYN);
    cudaFuncSetAttribute(tcgemm<1>, cudaFuncAttributeMaxDynamicSharedMemorySize, SMEM_DYN);

    // preprocessing
    split_kernel<<<EX / 1024, 256>>>(x, xh, xl);
    split_kernel<<<EW4 / 1024, 256>>>(Wf, Wfh, Wfl);
    split_kernel<<<EW4 / 1024, 256>>>(dWih, dih, dil);
    split_kernel<<<EW1 / 1024, 256>>>(Wdc, wdh, wdl);
    tsplit_kernel<<<dim3(HH / 32, FF / 32), dim3(32, 32)>>>(Wdc, wth, wtl);
    cvt16_kernel<<<EW4 / 1024, 256>>>(eWih, ei6);
    cvt16_kernel<<<EW4 / 1024, 256>>>(eWhh, eh6);
    cvt16_kernel<<<EW1 / 1024, 256>>>(Wdc, wd6);
    prep_kernel<<<NCAT, 128>>>(dWih, bdc, dbih, dbhh, ebih, ebhh, bdec0, bcat, benc);

    const dim3 gBig(G4 / 128, NROW / 128);    // 32 x 32
    const dim3 gOut(FF / 128, NROW / 128);    // 8 x 32
    const dim3 gFuse(NCAT / 128, NROW / 128); // 40 x 32
    const dim3 gWc(FF / 128, G4 / 128);       // 8 x 32
    const int  lstmGrid = NROW * HH / 4 / 256;

    Passes4 P;

    // 1) feats = relu(x @ Wf^T + bf): bf16 3-pass; emits bf16 pair + fp16 pair
    P.p[0] = { xh, xl, Wfh };  P.p[1] = { xh, nullptr, Wfl };
    tcgemm<0><<<gOut, 256, SMEM_DYN>>>(P, 2, INN, FF, bf, nullptr, 0,
                                       nullptr, 0, nullptr, 0,
                                       fh, fl, f6h, f6r, FF, 1.0f, 1);

    // 2) Wcomb = dWih @ Wdc + dWhh: bf16 3-pass -> bf16 pair rows 0..4095
    P.p[0] = { dih, dil, wth };  P.p[1] = { dih, nullptr, wtl };
    tcgemm<0><<<gWc, 256, SMEM_DYN>>>(P, 2, FF, FF, nullptr, dWhh, HH,
                                      nullptr, 0, nullptr, 0,
                                      wch, wcl, nullptr, nullptr, HH, 1.0f, 0);

    // 3) decoder step 0: gates = feats @ dWih^T + bdec0  (bf16 3-pass)
    P.p[0] = { fh, fl, dih };  P.p[1] = { fh, nullptr, dil };
    tcgemm<0><<<gBig, 256, SMEM_DYN>>>(P, 2, FF, G4, bdec0, nullptr, 0,
                                       gates, G4, nullptr, 0,
                                       nullptr, nullptr, nullptr, nullptr, 0, 1.0f, 0);
    lstm_kernel<<<lstmGrid, 256>>>(gates, nullptr, hh, hl, h6h, h6r, cbuf, nullptr);

    // 4) fused decoder steps (bf16 3-pass): [gates_{t+1} | out_t] = h_t @ [Wcomb ; Wdc]^T + bcat
    for (int t = 0; t < DD - 1; t++) {
        P.p[0] = { hh, hl, wch };  P.p[1] = { hh, nullptr, wcl };
        tcgemm<0><<<gFuse, 256, SMEM_DYN>>>(P, 2, HH, G4, bcat, nullptr, 0,
                                            gates, G4, dec_out + (size_t)t * FF, DD * FF,
                                            nullptr, nullptr, nullptr, nullptr, 0, 1.0f, 0);
        lstm_kernel<<<lstmGrid, 256>>>(gates, cbuf, hh, hl, h6h, h6r, cbuf, nullptr);
    }

    // 5) out_7 = h_7 @ Wdc^T + bdc  (fp16 2-pass); emits fp16 pair of (v/D) for encoder
    P.p[0] = { h6h, h6r, wd6 };
    tcgemm<1><<<gOut, 256, SMEM_DYN>>>(P, 1, HH, FF, bdc, nullptr, 0,
                                       dec_out + (size_t)(DD - 1) * FF, DD * FF, nullptr, 0,
                                       nullptr, nullptr, l6h, l6r, FF, 1.0f / (float)DD, 0);

    // 6) encoder gates = feats @ eWih^T + (last/D) @ eWhh^T + benc  (fp16, 2 duals = 4 passes)
    P.p[0] = { f6h, f6r, ei6 };  P.p[1] = { l6h, l6r, eh6 };
    tcgemm<1><<<gBig, 256, SMEM_DYN>>>(P, 2, FF, G4, benc, nullptr, 0,
                                       gates, G4, nullptr, 0,
                                       nullptr, nullptr, nullptr, nullptr, 0, 1.0f, 0);
    lstm_kernel<<<lstmGrid, 256>>>(gates, nullptr, hh, hl, h6h, h6r, cbuf, hfbuf);

    encscore_kernel<<<NROW / 8, 256>>>(hfbuf, Wec, bec, enc_out);
}